// round 13
// baseline (speedup 1.0000x reference)
#include <cuda_runtime.h>
#include <cuda_fp16.h>
#include <cstdint>

// ---------------- problem constants (capacities) ----------------
#define NMAX   50000
#define EMAX   1600000
#define DH     64
#define NG     64
#define NCLS   10
#define SCAN_B 256

// ---------------- device scratch (no allocations allowed) -------
// Invariant at kernel_launch entry (BSS zero-init on first call, restored
// at tails of consumers every call): g_degi=0, g_pool=0, g_cnt=0,
// g_ctr_scan=0, g_ctr_pool=0.
__device__ __half2 g_Ah1[NMAX * 32];     // ht1 table, fp16 (row = 128B)
__device__ __half2 g_Ah2[NMAX * 32];     // ht2 table, fp16
__device__ float   g_dis[NMAX];          // rsqrt(deg+1)
__device__ int     g_degi[NMAX];         // edge in-degree (no self loop)
__device__ int     g_rowtmp[NMAX];       // per-block exclusive scan
__device__ int     g_bsum[(NMAX + SCAN_B - 1) / SCAN_B];
__device__ int     g_rank[EMAX];         // per-edge rank within its dst row
__device__ int     g_csr[EMAX];          // (src << 7) byte offsets, grouped by dst
__device__ float4  g_pool[NG * 16];      // per-graph feature sums
__device__ float   g_cnt[NG];            // per-graph node counts
__device__ int     g_is32;               // 1 if indices are int32 on the wire
__device__ int     g_ctr_scan;           // last-block counter for scan
__device__ int     g_ctr_pool;           // last-block counter for pool->fc

// ---------------- helpers ----------------
__device__ __forceinline__ int load_idx(const void* p, long long i, int is32) {
    if (is32) return ((const int*)p)[i];
    return (int)((const long long*)p)[i];
}

__device__ __forceinline__ void red_add_v4(float* addr, float4 v) {
    asm volatile("red.global.add.v4.f32 [%0], {%1,%2,%3,%4};"
                 :: "l"(addr), "f"(v.x), "f"(v.y), "f"(v.z), "f"(v.w)
                 : "memory");
}

__device__ __forceinline__ void acc_u4(float* acc, uint4 u) {
    float2 f0 = __half22float2(((__half2*)&u)[0]);
    float2 f1 = __half22float2(((__half2*)&u)[1]);
    float2 f2 = __half22float2(((__half2*)&u)[2]);
    float2 f3 = __half22float2(((__half2*)&u)[3]);
    acc[0] += f0.x; acc[1] += f0.y; acc[2] += f1.x; acc[3] += f1.y;
    acc[4] += f2.x; acc[5] += f2.y; acc[6] += f3.x; acc[7] += f3.y;
}

__device__ __forceinline__ uint4 hadd4(uint4 a, uint4 b) {
    uint4 r;
    ((__half2*)&r)[0] = __hadd2(((__half2*)&a)[0], ((__half2*)&b)[0]);
    ((__half2*)&r)[1] = __hadd2(((__half2*)&a)[1], ((__half2*)&b)[1]);
    ((__half2*)&r)[2] = __hadd2(((__half2*)&a)[2], ((__half2*)&b)[2]);
    ((__half2*)&r)[3] = __hadd2(((__half2*)&a)[3], ((__half2*)&b)[3]);
    return r;
}

__device__ __forceinline__ int rowptr_of(int i) {
    return g_rowtmp[i] + g_bsum[i >> 8];
}

__device__ __forceinline__ uint4 pack8h(const float* v, float ds) {
    uint4 u;
    ((__half2*)&u)[0] = __floats2half2_rn(v[0] * ds, v[1] * ds);
    ((__half2*)&u)[1] = __floats2half2_rn(v[2] * ds, v[3] * ds);
    ((__half2*)&u)[2] = __floats2half2_rn(v[4] * ds, v[5] * ds);
    ((__half2*)&u)[3] = __floats2half2_rn(v[6] * ds, v[7] * ds);
    return u;
}

__device__ __forceinline__ uint4 gat(const char* base, int off, int l16) {
    return *(const uint4*)(base + off + l16);
}

// ---- tensor-core primitives ----
__device__ __forceinline__ uint32_t smem_u32(const void* p) {
    return (uint32_t)__cvta_generic_to_shared(p);
}

__device__ __forceinline__ void ldsm_x4(unsigned* r, uint32_t addr) {
    asm volatile("ldmatrix.sync.aligned.m8n8.x4.shared.b16 {%0,%1,%2,%3}, [%4];"
                 : "=r"(r[0]), "=r"(r[1]), "=r"(r[2]), "=r"(r[3]) : "r"(addr));
}

__device__ __forceinline__ void ldsm_x2t(unsigned* r, uint32_t addr) {
    asm volatile("ldmatrix.sync.aligned.m8n8.x2.trans.shared.b16 {%0,%1}, [%2];"
                 : "=r"(r[0]), "=r"(r[1]) : "r"(addr));
}

__device__ __forceinline__ void mma16816(float* d, const unsigned* a, const unsigned* b) {
    asm volatile("mma.sync.aligned.m16n8k16.row.col.f32.f16.f16.f32 "
                 "{%0,%1,%2,%3}, {%4,%5,%6,%7}, {%8,%9}, {%0,%1,%2,%3};"
                 : "+f"(d[0]), "+f"(d[1]), "+f"(d[2]), "+f"(d[3])
                 : "r"(a[0]), "r"(a[1]), "r"(a[2]), "r"(a[3]),
                   "r"(b[0]), "r"(b[1]));
}

#define LDP 72   // smem row pitch in halves (conflict-free ldmatrix)

// stage W[64][64] fp32 -> fp16 smem row-major, pitch LDP
__device__ __forceinline__ void stage_w(const float* __restrict__ W, __half* Ws) {
    for (int i2 = threadIdx.x; i2 < 64 * 32; i2 += blockDim.x) {
        int k = i2 >> 5, c = (i2 & 31) * 2;
        float2 w = ((const float2*)W)[i2];
        *(__half2*)(Ws + k * LDP + c) = __floats2half2_rn(w.x, w.y);
    }
}

// ---------------- kernels ----------------

// Launch 1: blocks [0, degB): deg count + rank (4 edges/thread);
// blocks [degB, ...): gemm1 via HMMA writing UNSCALED ht1.
__global__ void k_deg_gemm1(const float* __restrict__ X,
                            const float* __restrict__ W,
                            __half2* __restrict__ ht,
                            const void* __restrict__ ei,
                            int n, int E, int degB)
{
    __shared__ __align__(16) char sraw[2 * 64 * LDP * 2];   // 18KB

    if (blockIdx.x < degB) {
        int* flag = (int*)sraw;
        if (threadIdx.x == 0) *flag = 0;
        __syncthreads();
        long long probe = ((const long long*)ei)[threadIdx.x];
        if ((unsigned long long)probe > 0xFFFFFFFFull) *flag = 1;
        __syncthreads();
        int is32 = *flag;

        int t = blockIdx.x * blockDim.x + threadIdx.x;
        if (t == 0) g_is32 = is32;
        int e = t * 4;
        if (e >= E) return;

        int d[4], cnt;
        if (is32) {
            const int* dstp = (const int*)ei + E;
            if (e + 3 < E) {
                int4 dv = ((const int4*)dstp)[t];
                d[0] = dv.x; d[1] = dv.y; d[2] = dv.z; d[3] = dv.w; cnt = 4;
            } else {
                cnt = E - e;
                for (int i = 0; i < cnt; i++) d[i] = dstp[e + i];
            }
        } else {
            const long long* dstp = (const long long*)ei + E;
            if (e + 3 < E) {
                longlong2 d0 = ((const longlong2*)dstp)[t * 2];
                longlong2 d1 = ((const longlong2*)dstp)[t * 2 + 1];
                d[0] = (int)d0.x; d[1] = (int)d0.y;
                d[2] = (int)d1.x; d[3] = (int)d1.y;
                cnt = 4;
            } else {
                cnt = E - e;
                for (int i = 0; i < cnt; i++) d[i] = (int)dstp[e + i];
            }
        }
        if (cnt == 4) {
            int4 r;
            r.x = atomicAdd(&g_degi[d[0]], 1);
            r.y = atomicAdd(&g_degi[d[1]], 1);
            r.z = atomicAdd(&g_degi[d[2]], 1);
            r.w = atomicAdd(&g_degi[d[3]], 1);
            ((int4*)g_rank)[t] = r;
        } else {
            for (int i = 0; i < cnt; i++)
                g_rank[e + i] = atomicAdd(&g_degi[d[i]], 1);
        }
        return;
    }

    // ---- gemm1 via HMMA (UNSCALED output) ----
    __half* Ws = (__half*)sraw;
    __half* Xs = Ws + 64 * LDP;

    stage_w(W, Ws);

    int r0b = (blockIdx.x - degB) * 64;
    for (int i4 = threadIdx.x; i4 < 1024; i4 += blockDim.x) {
        int row = i4 >> 4, c4 = (i4 & 15) * 4;
        int grow = r0b + row;
        float4 xv = make_float4(0.f, 0.f, 0.f, 0.f);
        if (grow < n) xv = ((const float4*)(X + (size_t)grow * DH))[i4 & 15];
        *(__half2*)(Xs + row * LDP + c4)     = __floats2half2_rn(xv.x, xv.y);
        *(__half2*)(Xs + row * LDP + c4 + 2) = __floats2half2_rn(xv.z, xv.w);
    }
    __syncthreads();

    int w = threadIdx.x >> 5, lane = threadIdx.x & 31;
    int m0  = (w & 3) * 16;
    int n0b = (w >> 2) * 32;
    int r = lane & 7, q = lane >> 3;

    float d[4][4];
#pragma unroll
    for (int nt = 0; nt < 4; nt++)
#pragma unroll
        for (int i = 0; i < 4; i++) d[nt][i] = 0.f;

#pragma unroll
    for (int k0 = 0; k0 < 64; k0 += 16) {
        unsigned a[4];
        ldsm_x4(a, smem_u32(Xs + (m0 + r + (q & 1) * 8) * LDP
                               + k0 + (q >> 1) * 8));
#pragma unroll
        for (int nt = 0; nt < 4; nt++) {
            unsigned bf[2];
            ldsm_x2t(bf, smem_u32(Ws + (k0 + r + (q & 1) * 8) * LDP
                                     + n0b + nt * 8));
            mma16816(d[nt], a, bf);
        }
    }

    int g = lane >> 2, tg = lane & 3;
    int row0 = r0b + m0 + g, row1 = row0 + 8;
#pragma unroll
    for (int nt = 0; nt < 4; nt++) {
        int hcol = ((n0b + nt * 8) >> 1) + tg;
        if (row0 < n)
            ht[row0 * 32 + hcol] = __floats2half2_rn(d[nt][0], d[nt][1]);
        if (row1 < n)
            ht[row1 * 32 + hcol] = __floats2half2_rn(d[nt][2], d[nt][3]);
    }
}

// Launch 2: fused scan (per-block + last-block over block sums); dis.
__global__ void k_scan(int n) {
    __shared__ int ws[8];
    __shared__ int isLast;
    int i = blockIdx.x * SCAN_B + threadIdx.x;
    int v = (i < n) ? g_degi[i] : 0;
    int lane = threadIdx.x & 31, w = threadIdx.x >> 5;
    int x = v;
#pragma unroll
    for (int o = 1; o < 32; o <<= 1) {
        int y = __shfl_up_sync(~0u, x, o);
        if (lane >= o) x += y;
    }
    if (lane == 31) ws[w] = x;
    __syncthreads();
    if (w == 0) {
        int y = (lane < 8) ? ws[lane] : 0;
#pragma unroll
        for (int o = 1; o < 8; o <<= 1) {
            int z = __shfl_up_sync(~0u, y, o);
            if (lane >= o) y += z;
        }
        if (lane < 8) ws[lane] = y;
    }
    __syncthreads();
    int incl = x + (w > 0 ? ws[w - 1] : 0);
    if (i < n) {
        g_rowtmp[i] = incl - v;
        g_dis[i] = rsqrtf((float)(v + 1));
    }
    if (threadIdx.x == SCAN_B - 1) g_bsum[blockIdx.x] = incl;

    __threadfence();
    if (threadIdx.x == 0) {
        int d = atomicAdd(&g_ctr_scan, 1);
        isLast = (d == (int)gridDim.x - 1);
        if (isLast) g_ctr_scan = 0;
    }
    __syncthreads();
    if (!isLast) return;

    int nb = gridDim.x;
    int v2 = (threadIdx.x < nb) ? g_bsum[threadIdx.x] : 0;
    int x2 = v2;
#pragma unroll
    for (int o = 1; o < 32; o <<= 1) {
        int y = __shfl_up_sync(~0u, x2, o);
        if (lane >= o) x2 += y;
    }
    __syncthreads();
    if (lane == 31) ws[w] = x2;
    __syncthreads();
    if (w == 0) {
        int y = (lane < 8) ? ws[lane] : 0;
#pragma unroll
        for (int o = 1; o < 8; o <<= 1) {
            int z = __shfl_up_sync(~0u, y, o);
            if (lane >= o) y += z;
        }
        if (lane < 8) ws[lane] = y;
    }
    __syncthreads();
    int excl = x2 - v2 + (w > 0 ? ws[w - 1] : 0);
    if (threadIdx.x < nb) g_bsum[threadIdx.x] = excl;
}

// Launch 3: blocks [0, fillB): atomic-free CSR fill; blocks [fillB, ...):
// scale ht1 rows in place by dis[node] (fp16 hmul2).
__global__ void k_fill_scale(const void* __restrict__ ei,
                             __half2* __restrict__ ht,
                             int n, int E, int fillB)
{
    if (blockIdx.x < fillB) {
        int t = blockIdx.x * blockDim.x + threadIdx.x;
        int e = t * 4;
        if (e >= E) return;
        int is32 = g_is32;
        int s[4], d[4], r[4], cnt;
        if (is32) {
            const int* srcp = (const int*)ei;
            const int* dstp = srcp + E;
            if (e + 3 < E) {
                int4 sv = ((const int4*)srcp)[t];
                int4 dv = ((const int4*)dstp)[t];
                int4 rv = ((const int4*)g_rank)[t];
                s[0] = sv.x; s[1] = sv.y; s[2] = sv.z; s[3] = sv.w;
                d[0] = dv.x; d[1] = dv.y; d[2] = dv.z; d[3] = dv.w;
                r[0] = rv.x; r[1] = rv.y; r[2] = rv.z; r[3] = rv.w;
                cnt = 4;
            } else {
                cnt = E - e;
                for (int i = 0; i < cnt; i++) {
                    s[i] = srcp[e + i]; d[i] = dstp[e + i]; r[i] = g_rank[e + i];
                }
            }
        } else {
            const long long* srcp = (const long long*)ei;
            const long long* dstp = srcp + E;
            if (e + 3 < E) {
                longlong2 s0 = ((const longlong2*)srcp)[t * 2];
                longlong2 s1 = ((const longlong2*)srcp)[t * 2 + 1];
                longlong2 d0 = ((const longlong2*)dstp)[t * 2];
                longlong2 d1 = ((const longlong2*)dstp)[t * 2 + 1];
                int4 rv = ((const int4*)g_rank)[t];
                s[0] = (int)s0.x; s[1] = (int)s0.y; s[2] = (int)s1.x; s[3] = (int)s1.y;
                d[0] = (int)d0.x; d[1] = (int)d0.y; d[2] = (int)d1.x; d[3] = (int)d1.y;
                r[0] = rv.x; r[1] = rv.y; r[2] = rv.z; r[3] = rv.w;
                cnt = 4;
            } else {
                cnt = E - e;
                for (int i = 0; i < cnt; i++) {
                    s[i] = (int)srcp[e + i]; d[i] = (int)dstp[e + i]; r[i] = g_rank[e + i];
                }
            }
        }
#pragma unroll
        for (int i = 0; i < 4; i++) {
            if (i < cnt) {
                int p = rowptr_of(d[i]) + r[i];
                g_csr[p] = s[i] << 7;
            }
        }
        return;
    }

    // ---- scale: ht1[node] *= dis[node] ----
    int node = (blockIdx.x - fillB) * blockDim.x + threadIdx.x;
    if (node >= n) return;
    __half2 dsh = __float2half2_rn(g_dis[node]);
    uint4* row = (uint4*)((__half*)ht + (size_t)node * DH);
#pragma unroll
    for (int j = 0; j < 8; j++) {
        uint4 u = row[j];
        ((__half2*)&u)[0] = __hmul2(((__half2*)&u)[0], dsh);
        ((__half2*)&u)[1] = __hmul2(((__half2*)&u)[1], dsh);
        ((__half2*)&u)[2] = __hmul2(((__half2*)&u)[2], dsh);
        ((__half2*)&u)[3] = __hmul2(((__half2*)&u)[3], dsh);
        row[j] = u;
    }
}

// shared gather-sum: fp32 acc[8] = sum of ht rows (self + neighbors)
__device__ __forceinline__ void gather_sum(const __half2* __restrict__ ht,
                                           int node, int l, float* acc)
{
    const char* hb = (const char*)ht;
    int l16 = l << 4;
#pragma unroll
    for (int j = 0; j < 8; j++) acc[j] = 0.f;
    acc_u4(acc, gat(hb, node << 7, l16));   // self loop

    int k = rowptr_of(node);
    int e = k + g_degi[node];
    for (; k + 8 <= e; k += 8) {
        int o0 = g_csr[k],     o1 = g_csr[k + 1];
        int o2 = g_csr[k + 2], o3 = g_csr[k + 3];
        int o4 = g_csr[k + 4], o5 = g_csr[k + 5];
        int o6 = g_csr[k + 6], o7 = g_csr[k + 7];
        uint4 v0 = gat(hb, o0, l16), v1 = gat(hb, o1, l16);
        uint4 v2 = gat(hb, o2, l16), v3 = gat(hb, o3, l16);
        uint4 v4 = gat(hb, o4, l16), v5 = gat(hb, o5, l16);
        uint4 v6 = gat(hb, o6, l16), v7 = gat(hb, o7, l16);
        uint4 t0 = hadd4(hadd4(v0, v1), hadd4(v2, v3));
        uint4 t1 = hadd4(hadd4(v4, v5), hadd4(v6, v7));
        acc_u4(acc, hadd4(t0, t1));
    }
    for (; k + 4 <= e; k += 4) {
        int o0 = g_csr[k],     o1 = g_csr[k + 1];
        int o2 = g_csr[k + 2], o3 = g_csr[k + 3];
        uint4 v0 = gat(hb, o0, l16), v1 = gat(hb, o1, l16);
        uint4 v2 = gat(hb, o2, l16), v3 = gat(hb, o3, l16);
        acc_u4(acc, hadd4(hadd4(v0, v1), hadd4(v2, v3)));
    }
    for (; k < e; k++) acc_u4(acc, gat(hb, g_csr[k], l16));
}

// Launch 4: agg over ht1 -> h1 (smem fp16) -> HMMA gemv W2 -> ht2 (fp16).
__global__ void k_agg1_gemm2(const __half2* __restrict__ ht1,
                             const float* __restrict__ b,
                             const float* __restrict__ W2,
                             __half2* __restrict__ ht2, int n)
{
    __shared__ __half sb[64 * LDP + 32 * LDP];   // W2 (9KB) + h1 tile (4.5KB)
    __half* Ws  = sb;
    __half* h1s = sb + 64 * LDP;

    stage_w(W2, Ws);

    int node_l = threadIdx.x >> 3;
    int node = blockIdx.x * 32 + node_l;
    int l = threadIdx.x & 7;

    float hv[8];
#pragma unroll
    for (int j = 0; j < 8; j++) hv[j] = 0.f;

    if (node < n) {
        float acc[8];
        gather_sum(ht1, node, l, acc);
        float ds = g_dis[node];
        const float4* b4 = (const float4*)b;
        float4 b0 = b4[l * 2], b1 = b4[l * 2 + 1];
        hv[0] = fmaxf(acc[0] * ds + b0.x, 0.f);
        hv[1] = fmaxf(acc[1] * ds + b0.y, 0.f);
        hv[2] = fmaxf(acc[2] * ds + b0.z, 0.f);
        hv[3] = fmaxf(acc[3] * ds + b0.w, 0.f);
        hv[4] = fmaxf(acc[4] * ds + b1.x, 0.f);
        hv[5] = fmaxf(acc[5] * ds + b1.y, 0.f);
        hv[6] = fmaxf(acc[6] * ds + b1.z, 0.f);
        hv[7] = fmaxf(acc[7] * ds + b1.w, 0.f);
    }
    *(uint4*)(h1s + node_l * LDP + l * 8) = pack8h(hv, 1.0f);
    __syncthreads();

    int w = threadIdx.x >> 5, lane = threadIdx.x & 31;
    int m0  = (w & 1) * 16;
    int n0b = (w >> 1) * 16;
    int r = lane & 7, q = lane >> 3;

    float d[2][4];
#pragma unroll
    for (int nt = 0; nt < 2; nt++)
#pragma unroll
        for (int i = 0; i < 4; i++) d[nt][i] = 0.f;

#pragma unroll
    for (int k0 = 0; k0 < 64; k0 += 16) {
        unsigned a[4];
        ldsm_x4(a, smem_u32(h1s + (m0 + r + (q & 1) * 8) * LDP
                               + k0 + (q >> 1) * 8));
#pragma unroll
        for (int nt = 0; nt < 2; nt++) {
            unsigned bf[2];
            ldsm_x2t(bf, smem_u32(Ws + (k0 + r + (q & 1) * 8) * LDP
                                     + n0b + nt * 8));
            mma16816(d[nt], a, bf);
        }
    }

    int g = lane >> 2, tg = lane & 3;
    int nd0 = blockIdx.x * 32 + m0 + g, nd1 = nd0 + 8;
    float ds0 = (nd0 < n) ? g_dis[nd0] : 0.f;
    float ds1 = (nd1 < n) ? g_dis[nd1] : 0.f;
#pragma unroll
    for (int nt = 0; nt < 2; nt++) {
        int hcol = ((n0b + nt * 8) >> 1) + tg;
        if (nd0 < n)
            ht2[nd0 * 32 + hcol] = __floats2half2_rn(d[nt][0] * ds0, d[nt][1] * ds0);
        if (nd1 < n)
            ht2[nd1 * 32 + hcol] = __floats2half2_rn(d[nt][2] * ds1, d[nt][3] * ds1);
    }
}

// Launch 5: agg layer 2 + warp-reduced pool atomics; LAST block does FC.
__global__ void k_agg_pool_fc(const __half2* __restrict__ ht,
                              const float* __restrict__ b,
                              const void* __restrict__ batch,
                              const float* __restrict__ Wfc,
                              const float* __restrict__ bfc,
                              float* __restrict__ out, int n)
{
    int t = blockIdx.x * blockDim.x + threadIdx.x;
    int node = t >> 3;
    int l = t & 7;
    int lane = threadIdx.x & 31;

    float4 r0 = make_float4(0.f, 0.f, 0.f, 0.f);
    float4 r1 = make_float4(0.f, 0.f, 0.f, 0.f);
    int gph = -1;

    if (node < n) {
        float acc[8];
        gather_sum(ht, node, l, acc);

        float ds = g_dis[node];
        const float4* b4 = (const float4*)b;
        float4 b0 = b4[l * 2], b1 = b4[l * 2 + 1];
        r0.x = fmaxf(acc[0] * ds + b0.x, 0.f);
        r0.y = fmaxf(acc[1] * ds + b0.y, 0.f);
        r0.z = fmaxf(acc[2] * ds + b0.z, 0.f);
        r0.w = fmaxf(acc[3] * ds + b0.w, 0.f);
        r1.x = fmaxf(acc[4] * ds + b1.x, 0.f);
        r1.y = fmaxf(acc[5] * ds + b1.y, 0.f);
        r1.z = fmaxf(acc[6] * ds + b1.z, 0.f);
        r1.w = fmaxf(acc[7] * ds + b1.w, 0.f);

        gph = load_idx(batch, node, g_is32);
        if (l == 0) g_degi[node] = 0;    // restore zero-state for next replay
    }

    // ---- warp-level pool reduction (batch is sorted -> usually uniform) ----
    int g0 = __shfl_sync(~0u, gph, 0);
    bool uni = __all_sync(~0u, gph == g0);

    if (uni && g0 >= 0) {
#pragma unroll
        for (int o = 16; o >= 8; o >>= 1) {
            r0.x += __shfl_down_sync(~0u, r0.x, o);
            r0.y += __shfl_down_sync(~0u, r0.y, o);
            r0.z += __shfl_down_sync(~0u, r0.z, o);
            r0.w += __shfl_down_sync(~0u, r0.w, o);
            r1.x += __shfl_down_sync(~0u, r1.x, o);
            r1.y += __shfl_down_sync(~0u, r1.y, o);
            r1.z += __shfl_down_sync(~0u, r1.z, o);
            r1.w += __shfl_down_sync(~0u, r1.w, o);
        }
        if (lane < 8) {
            float* pp = (float*)g_pool + (size_t)g0 * DH + lane * 8;
            red_add_v4(pp, r0);
            red_add_v4(pp + 4, r1);
            if (lane == 0) atomicAdd(&g_cnt[g0], 4.0f);
        }
    } else if (gph >= 0) {
        float* pp = (float*)g_pool + (size_t)gph * DH + l * 8;
        red_add_v4(pp, r0);
        red_add_v4(pp + 4, r1);
        if (l == 0) atomicAdd(&g_cnt[gph], 1.0f);
    }

    // ---- last-block election, then FC ----
    __threadfence();
    __shared__ int isLast;
    if (threadIdx.x == 0) {
        int d = atomicAdd(&g_ctr_pool, 1);
        isLast = (d == (int)gridDim.x - 1);
        if (isLast) g_ctr_pool = 0;
    }
    __syncthreads();
    if (!isLast) return;

    for (int i = threadIdx.x; i < NG * NCLS; i += blockDim.x) {
        int g2 = i / NCLS, c = i % NCLS;
        float inv = 1.0f / fmaxf(g_cnt[g2], 1.0f);
        const float* pr = (const float*)g_pool + (size_t)g2 * DH;
        float acc = 0.f;
#pragma unroll
        for (int j = 0; j < DH; j++) acc += pr[j] * Wfc[j * NCLS + c];
        out[i] = acc * inv + bfc[c];
    }
    __syncthreads();
    for (int i = threadIdx.x; i < NG * 16; i += blockDim.x)
        g_pool[i] = make_float4(0.f, 0.f, 0.f, 0.f);
    if (threadIdx.x < NG) g_cnt[threadIdx.x] = 0.0f;
}

// ---------------- launcher ----------------
extern "C" void kernel_launch(void* const* d_in, const int* in_sizes, int n_in,
                              void* d_out, int out_size)
{
    const float* x   = (const float*)d_in[0];
    const void*  ei  = d_in[1];
    const void*  bat = d_in[2];
    const float* W1  = (const float*)d_in[3];
    const float* b1  = (const float*)d_in[4];
    const float* W2  = (const float*)d_in[5];
    const float* b2  = (const float*)d_in[6];
    const float* Wfc = (const float*)d_in[7];
    const float* bfc = (const float*)d_in[8];
    float* out = (float*)d_out;

    int n = in_sizes[0] / DH;       // nodes
    int E = in_sizes[1] / 2;        // edges

    static __half2* pA1 = nullptr; static __half2* pA2 = nullptr;
    if (!pA1) {
        void* tmp;
        cudaGetSymbolAddress(&tmp, g_Ah1); pA1 = (__half2*)tmp;
        cudaGetSymbolAddress(&tmp, g_Ah2); pA2 = (__half2*)tmp;
    }

    const int TB = 256;
    int nb_scan = (n + SCAN_B - 1) / SCAN_B;
    int q_e_blocks = ((E + 3) / 4 + TB - 1) / TB;
    int gemm_blocks = (n + 63) / 64;
    int scale_blocks = (n + TB - 1) / TB;
    int fused_blocks = (n + 31) / 32;
    int agg_blocks = ((long long)n * 8 + TB - 1) / TB;

    k_deg_gemm1<<<q_e_blocks + gemm_blocks, TB>>>(x, W1, pA1, ei,
                                                  n, E, q_e_blocks);      // 1
    k_scan<<<nb_scan, SCAN_B>>>(n);                                       // 2
    k_fill_scale<<<q_e_blocks + scale_blocks, TB>>>(ei, pA1, n, E,
                                                    q_e_blocks);          // 3
    k_agg1_gemm2<<<fused_blocks, TB>>>(pA1, b1, W2, pA2, n);              // 4
    k_agg_pool_fc<<<agg_blocks, TB>>>(pA2, b2, bat, Wfc, bfc, out, n);    // 5
}

// round 14
// speedup vs baseline: 1.0428x; 1.0428x over previous
#include <cuda_runtime.h>
#include <cuda_fp16.h>
#include <cstdint>

// ---------------- problem constants (capacities) ----------------
#define NMAX   50000
#define EMAX   1600000
#define DH     64
#define NG     64
#define NCLS   10
#define SCAN_B 256

// ---------------- device scratch (no allocations allowed) -------
// Invariant at kernel_launch entry (BSS zero-init on first call, restored
// at tails of consumers every call): g_degi=0, g_pool=0, g_cnt=0,
// g_ctr_scan=0, g_ctr_pool=0.
__device__ __half2 g_Ah1[NMAX * 32];     // ht1 table, fp16 (row = 128B)
__device__ __half2 g_Ah2[NMAX * 32];     // ht2 table, fp16
__device__ float   g_dis[NMAX];          // rsqrt(deg+1)
__device__ int     g_degi[NMAX];         // edge in-degree (no self loop)
__device__ int     g_rowtmp[NMAX];       // per-block exclusive scan
__device__ int     g_bsum[(NMAX + SCAN_B - 1) / SCAN_B];
__device__ int     g_rank[EMAX];         // per-edge rank within its dst row
__device__ int     g_csr[EMAX];          // (src << 7) byte offsets, grouped by dst
__device__ float4  g_pool[NG * 16];      // per-graph feature sums
__device__ float   g_cnt[NG];            // per-graph node counts
__device__ int     g_is32;               // 1 if indices are int32 on the wire
__device__ int     g_ctr_scan;           // last-block counter for scan
__device__ int     g_ctr_pool;           // last-block counter for pool->fc

// ---------------- helpers ----------------
__device__ __forceinline__ int load_idx(const void* p, long long i, int is32) {
    if (is32) return ((const int*)p)[i];
    return (int)((const long long*)p)[i];
}

__device__ __forceinline__ void red_add_v4(float* addr, float4 v) {
    asm volatile("red.global.add.v4.f32 [%0], {%1,%2,%3,%4};"
                 :: "l"(addr), "f"(v.x), "f"(v.y), "f"(v.z), "f"(v.w)
                 : "memory");
}

__device__ __forceinline__ void acc_u4(float* acc, uint4 u) {
    float2 f0 = __half22float2(((__half2*)&u)[0]);
    float2 f1 = __half22float2(((__half2*)&u)[1]);
    float2 f2 = __half22float2(((__half2*)&u)[2]);
    float2 f3 = __half22float2(((__half2*)&u)[3]);
    acc[0] += f0.x; acc[1] += f0.y; acc[2] += f1.x; acc[3] += f1.y;
    acc[4] += f2.x; acc[5] += f2.y; acc[6] += f3.x; acc[7] += f3.y;
}

__device__ __forceinline__ uint4 hadd4(uint4 a, uint4 b) {
    uint4 r;
    ((__half2*)&r)[0] = __hadd2(((__half2*)&a)[0], ((__half2*)&b)[0]);
    ((__half2*)&r)[1] = __hadd2(((__half2*)&a)[1], ((__half2*)&b)[1]);
    ((__half2*)&r)[2] = __hadd2(((__half2*)&a)[2], ((__half2*)&b)[2]);
    ((__half2*)&r)[3] = __hadd2(((__half2*)&a)[3], ((__half2*)&b)[3]);
    return r;
}

__device__ __forceinline__ int rowptr_of(int i) {
    return g_rowtmp[i] + g_bsum[i >> 8];
}

__device__ __forceinline__ uint4 pack8h(const float* v, float ds) {
    uint4 u;
    ((__half2*)&u)[0] = __floats2half2_rn(v[0] * ds, v[1] * ds);
    ((__half2*)&u)[1] = __floats2half2_rn(v[2] * ds, v[3] * ds);
    ((__half2*)&u)[2] = __floats2half2_rn(v[4] * ds, v[5] * ds);
    ((__half2*)&u)[3] = __floats2half2_rn(v[6] * ds, v[7] * ds);
    return u;
}

__device__ __forceinline__ uint4 gat(const char* base, int off, int l16) {
    return *(const uint4*)(base + off + l16);
}

// ---- tensor-core primitives ----
__device__ __forceinline__ uint32_t smem_u32(const void* p) {
    return (uint32_t)__cvta_generic_to_shared(p);
}

__device__ __forceinline__ void ldsm_x4(unsigned* r, uint32_t addr) {
    asm volatile("ldmatrix.sync.aligned.m8n8.x4.shared.b16 {%0,%1,%2,%3}, [%4];"
                 : "=r"(r[0]), "=r"(r[1]), "=r"(r[2]), "=r"(r[3]) : "r"(addr));
}

__device__ __forceinline__ void ldsm_x2t(unsigned* r, uint32_t addr) {
    asm volatile("ldmatrix.sync.aligned.m8n8.x2.trans.shared.b16 {%0,%1}, [%2];"
                 : "=r"(r[0]), "=r"(r[1]) : "r"(addr));
}

__device__ __forceinline__ void mma16816(float* d, const unsigned* a, const unsigned* b) {
    asm volatile("mma.sync.aligned.m16n8k16.row.col.f32.f16.f16.f32 "
                 "{%0,%1,%2,%3}, {%4,%5,%6,%7}, {%8,%9}, {%0,%1,%2,%3};"
                 : "+f"(d[0]), "+f"(d[1]), "+f"(d[2]), "+f"(d[3])
                 : "r"(a[0]), "r"(a[1]), "r"(a[2]), "r"(a[3]),
                   "r"(b[0]), "r"(b[1]));
}

#define LDP 72   // smem row pitch in halves (conflict-free ldmatrix)

// stage W[64][64] fp32 -> fp16 smem row-major, pitch LDP
__device__ __forceinline__ void stage_w(const float* __restrict__ W, __half* Ws) {
    for (int i2 = threadIdx.x; i2 < 64 * 32; i2 += blockDim.x) {
        int k = i2 >> 5, c = (i2 & 31) * 2;
        float2 w = ((const float2*)W)[i2];
        *(__half2*)(Ws + k * LDP + c) = __floats2half2_rn(w.x, w.y);
    }
}

// ---------------- kernels ----------------

// deg[dst] += 1 over edges, recording per-edge rank. 4 edges/thread.
__global__ void k_deg(const void* __restrict__ ei, int E) {
    __shared__ int flag;
    if (threadIdx.x == 0) flag = 0;
    __syncthreads();
    long long probe = ((const long long*)ei)[threadIdx.x];
    if ((unsigned long long)probe > 0xFFFFFFFFull) flag = 1;
    __syncthreads();
    int is32 = flag;

    int t = blockIdx.x * blockDim.x + threadIdx.x;
    if (t == 0) g_is32 = is32;
    int e = t * 4;
    if (e >= E) return;

    int d[4], cnt;
    if (is32) {
        const int* dstp = (const int*)ei + E;
        if (e + 3 < E) {
            int4 dv = ((const int4*)dstp)[t];
            d[0] = dv.x; d[1] = dv.y; d[2] = dv.z; d[3] = dv.w; cnt = 4;
        } else {
            cnt = E - e;
            for (int i = 0; i < cnt; i++) d[i] = dstp[e + i];
        }
    } else {
        const long long* dstp = (const long long*)ei + E;
        if (e + 3 < E) {
            longlong2 d0 = ((const longlong2*)dstp)[t * 2];
            longlong2 d1 = ((const longlong2*)dstp)[t * 2 + 1];
            d[0] = (int)d0.x; d[1] = (int)d0.y; d[2] = (int)d1.x; d[3] = (int)d1.y;
            cnt = 4;
        } else {
            cnt = E - e;
            for (int i = 0; i < cnt; i++) d[i] = (int)dstp[e + i];
        }
    }

    if (cnt == 4) {
        int4 r;
        r.x = atomicAdd(&g_degi[d[0]], 1);
        r.y = atomicAdd(&g_degi[d[1]], 1);
        r.z = atomicAdd(&g_degi[d[2]], 1);
        r.w = atomicAdd(&g_degi[d[3]], 1);
        ((int4*)g_rank)[t] = r;
    } else {
        for (int i = 0; i < cnt; i++)
            g_rank[e + i] = atomicAdd(&g_degi[d[i]], 1);
    }
}

// Fused scan: per-block exclusive scan + dis; last block scans block sums.
__global__ void k_scan(int n) {
    __shared__ int ws[8];
    __shared__ int isLast;
    int i = blockIdx.x * SCAN_B + threadIdx.x;
    int v = (i < n) ? g_degi[i] : 0;
    int lane = threadIdx.x & 31, w = threadIdx.x >> 5;
    int x = v;
#pragma unroll
    for (int o = 1; o < 32; o <<= 1) {
        int y = __shfl_up_sync(~0u, x, o);
        if (lane >= o) x += y;
    }
    if (lane == 31) ws[w] = x;
    __syncthreads();
    if (w == 0) {
        int y = (lane < 8) ? ws[lane] : 0;
#pragma unroll
        for (int o = 1; o < 8; o <<= 1) {
            int z = __shfl_up_sync(~0u, y, o);
            if (lane >= o) y += z;
        }
        if (lane < 8) ws[lane] = y;
    }
    __syncthreads();
    int incl = x + (w > 0 ? ws[w - 1] : 0);
    if (i < n) {
        g_rowtmp[i] = incl - v;
        g_dis[i] = rsqrtf((float)(v + 1));
    }
    if (threadIdx.x == SCAN_B - 1) g_bsum[blockIdx.x] = incl;

    __threadfence();
    if (threadIdx.x == 0) {
        int d = atomicAdd(&g_ctr_scan, 1);
        isLast = (d == (int)gridDim.x - 1);
        if (isLast) g_ctr_scan = 0;
    }
    __syncthreads();
    if (!isLast) return;

    int nb = gridDim.x;
    int v2 = (threadIdx.x < nb) ? g_bsum[threadIdx.x] : 0;
    int x2 = v2;
#pragma unroll
    for (int o = 1; o < 32; o <<= 1) {
        int y = __shfl_up_sync(~0u, x2, o);
        if (lane >= o) x2 += y;
    }
    __syncthreads();
    if (lane == 31) ws[w] = x2;
    __syncthreads();
    if (w == 0) {
        int y = (lane < 8) ? ws[lane] : 0;
#pragma unroll
        for (int o = 1; o < 8; o <<= 1) {
            int z = __shfl_up_sync(~0u, y, o);
            if (lane >= o) y += z;
        }
        if (lane < 8) ws[lane] = y;
    }
    __syncthreads();
    int excl = x2 - v2 + (w > 0 ? ws[w - 1] : 0);
    if (threadIdx.x < nb) g_bsum[threadIdx.x] = excl;
}

// Combined: blocks [0, gemmB) gemm1 via HMMA; rest: atomic-free CSR fill.
__global__ void k_gemm1_fill(const float* __restrict__ X,
                             const float* __restrict__ W,
                             __half2* __restrict__ ht,
                             const void* __restrict__ ei,
                             int n, int E, int gemmB)
{
    if (blockIdx.x < gemmB) {
        __shared__ __half sb[2 * 64 * LDP];   // 18KB: W1 + X tile
        __half* Ws = sb;
        __half* Xs = sb + 64 * LDP;

        stage_w(W, Ws);

        int r0b = blockIdx.x * 64;
        for (int i4 = threadIdx.x; i4 < 1024; i4 += blockDim.x) {
            int row = i4 >> 4, c4 = (i4 & 15) * 4;
            int grow = r0b + row;
            float4 xv = make_float4(0.f, 0.f, 0.f, 0.f);
            if (grow < n) xv = ((const float4*)(X + (size_t)grow * DH))[i4 & 15];
            *(__half2*)(Xs + row * LDP + c4)     = __floats2half2_rn(xv.x, xv.y);
            *(__half2*)(Xs + row * LDP + c4 + 2) = __floats2half2_rn(xv.z, xv.w);
        }
        __syncthreads();

        int w = threadIdx.x >> 5, lane = threadIdx.x & 31;
        int m0  = (w & 3) * 16;
        int n0b = (w >> 2) * 32;
        int r = lane & 7, q = lane >> 3;

        float d[4][4];
#pragma unroll
        for (int nt = 0; nt < 4; nt++)
#pragma unroll
            for (int i = 0; i < 4; i++) d[nt][i] = 0.f;

#pragma unroll
        for (int k0 = 0; k0 < 64; k0 += 16) {
            unsigned a[4];
            ldsm_x4(a, smem_u32(Xs + (m0 + r + (q & 1) * 8) * LDP
                                   + k0 + (q >> 1) * 8));
#pragma unroll
            for (int nt = 0; nt < 4; nt++) {
                unsigned bf[2];
                ldsm_x2t(bf, smem_u32(Ws + (k0 + r + (q & 1) * 8) * LDP
                                         + n0b + nt * 8));
                mma16816(d[nt], a, bf);
            }
        }

        int g = lane >> 2, tg = lane & 3;
        int row0 = r0b + m0 + g, row1 = row0 + 8;
        float ds0 = (row0 < n) ? g_dis[row0] : 0.f;
        float ds1 = (row1 < n) ? g_dis[row1] : 0.f;
#pragma unroll
        for (int nt = 0; nt < 4; nt++) {
            int hcol = ((n0b + nt * 8) >> 1) + tg;
            if (row0 < n)
                ht[row0 * 32 + hcol] = __floats2half2_rn(d[nt][0] * ds0, d[nt][1] * ds0);
            if (row1 < n)
                ht[row1 * 32 + hcol] = __floats2half2_rn(d[nt][2] * ds1, d[nt][3] * ds1);
        }
        return;
    }

    // ---- fill: atomic-free CSR scatter, 4 edges/thread ----
    int t = (blockIdx.x - gemmB) * blockDim.x + threadIdx.x;
    int e = t * 4;
    if (e >= E) return;
    int is32 = g_is32;
    int s[4], d[4], r[4], cnt;
    if (is32) {
        const int* srcp = (const int*)ei;
        const int* dstp = srcp + E;
        if (e + 3 < E) {
            int4 sv = ((const int4*)srcp)[t];
            int4 dv = ((const int4*)dstp)[t];
            int4 rv = ((const int4*)g_rank)[t];
            s[0] = sv.x; s[1] = sv.y; s[2] = sv.z; s[3] = sv.w;
            d[0] = dv.x; d[1] = dv.y; d[2] = dv.z; d[3] = dv.w;
            r[0] = rv.x; r[1] = rv.y; r[2] = rv.z; r[3] = rv.w;
            cnt = 4;
        } else {
            cnt = E - e;
            for (int i = 0; i < cnt; i++) {
                s[i] = srcp[e + i]; d[i] = dstp[e + i]; r[i] = g_rank[e + i];
            }
        }
    } else {
        const long long* srcp = (const long long*)ei;
        const long long* dstp = srcp + E;
        if (e + 3 < E) {
            longlong2 s0 = ((const longlong2*)srcp)[t * 2];
            longlong2 s1 = ((const longlong2*)srcp)[t * 2 + 1];
            longlong2 d0 = ((const longlong2*)dstp)[t * 2];
            longlong2 d1 = ((const longlong2*)dstp)[t * 2 + 1];
            int4 rv = ((const int4*)g_rank)[t];
            s[0] = (int)s0.x; s[1] = (int)s0.y; s[2] = (int)s1.x; s[3] = (int)s1.y;
            d[0] = (int)d0.x; d[1] = (int)d0.y; d[2] = (int)d1.x; d[3] = (int)d1.y;
            r[0] = rv.x; r[1] = rv.y; r[2] = rv.z; r[3] = rv.w;
            cnt = 4;
        } else {
            cnt = E - e;
            for (int i = 0; i < cnt; i++) {
                s[i] = (int)srcp[e + i]; d[i] = (int)dstp[e + i]; r[i] = g_rank[e + i];
            }
        }
    }
#pragma unroll
    for (int i = 0; i < 4; i++) {
        if (i < cnt) {
            int p = rowptr_of(d[i]) + r[i];
            g_csr[p] = s[i] << 7;
        }
    }
}

// shared gather-sum: fp32 acc[8] = sum of ht rows (self + neighbors)
__device__ __forceinline__ void gather_sum(const __half2* __restrict__ ht,
                                           int node, int l, float* acc)
{
    const char* hb = (const char*)ht;
    int l16 = l << 4;
#pragma unroll
    for (int j = 0; j < 8; j++) acc[j] = 0.f;
    acc_u4(acc, gat(hb, node << 7, l16));   // self loop

    int k = rowptr_of(node);
    int e = k + g_degi[node];
    for (; k + 8 <= e; k += 8) {
        int o0 = g_csr[k],     o1 = g_csr[k + 1];
        int o2 = g_csr[k + 2], o3 = g_csr[k + 3];
        int o4 = g_csr[k + 4], o5 = g_csr[k + 5];
        int o6 = g_csr[k + 6], o7 = g_csr[k + 7];
        uint4 v0 = gat(hb, o0, l16), v1 = gat(hb, o1, l16);
        uint4 v2 = gat(hb, o2, l16), v3 = gat(hb, o3, l16);
        uint4 v4 = gat(hb, o4, l16), v5 = gat(hb, o5, l16);
        uint4 v6 = gat(hb, o6, l16), v7 = gat(hb, o7, l16);
        uint4 t0 = hadd4(hadd4(v0, v1), hadd4(v2, v3));
        uint4 t1 = hadd4(hadd4(v4, v5), hadd4(v6, v7));
        acc_u4(acc, hadd4(t0, t1));
    }
    for (; k + 4 <= e; k += 4) {
        int o0 = g_csr[k],     o1 = g_csr[k + 1];
        int o2 = g_csr[k + 2], o3 = g_csr[k + 3];
        uint4 v0 = gat(hb, o0, l16), v1 = gat(hb, o1, l16);
        uint4 v2 = gat(hb, o2, l16), v3 = gat(hb, o3, l16);
        acc_u4(acc, hadd4(hadd4(v0, v1), hadd4(v2, v3)));
    }
    for (; k < e; k++) acc_u4(acc, gat(hb, g_csr[k], l16));
}

// Fused: agg over ht1 -> h1 (smem fp16) -> HMMA gemv W2 -> ht2 (fp16).
// 512 threads = 64 nodes/block; 16 warps cover the 64x64 gemv tile.
__global__ void k_agg1_gemm2(const __half2* __restrict__ ht1,
                             const float* __restrict__ b,
                             const float* __restrict__ W2,
                             __half2* __restrict__ ht2, int n)
{
    __shared__ __half sb[64 * LDP + 64 * LDP];   // W2 (9KB) + h1 tile (9KB)
    __half* Ws  = sb;
    __half* h1s = sb + 64 * LDP;

    stage_w(W2, Ws);

    int node_l = threadIdx.x >> 3;          // 0..63
    int node = blockIdx.x * 64 + node_l;
    int l = threadIdx.x & 7;

    float hv[8];
#pragma unroll
    for (int j = 0; j < 8; j++) hv[j] = 0.f;

    if (node < n) {
        float acc[8];
        gather_sum(ht1, node, l, acc);
        float ds = g_dis[node];
        const float4* b4 = (const float4*)b;
        float4 b0 = b4[l * 2], b1 = b4[l * 2 + 1];
        hv[0] = fmaxf(acc[0] * ds + b0.x, 0.f);
        hv[1] = fmaxf(acc[1] * ds + b0.y, 0.f);
        hv[2] = fmaxf(acc[2] * ds + b0.z, 0.f);
        hv[3] = fmaxf(acc[3] * ds + b0.w, 0.f);
        hv[4] = fmaxf(acc[4] * ds + b1.x, 0.f);
        hv[5] = fmaxf(acc[5] * ds + b1.y, 0.f);
        hv[6] = fmaxf(acc[6] * ds + b1.z, 0.f);
        hv[7] = fmaxf(acc[7] * ds + b1.w, 0.f);
    }
    *(uint4*)(h1s + node_l * LDP + l * 8) = pack8h(hv, 1.0f);
    __syncthreads();

    int w = threadIdx.x >> 5, lane = threadIdx.x & 31;
    int m0  = (w & 3) * 16;                 // 4 row-groups of 16
    int n0b = (w >> 2) * 16;                // 4 col-groups of 16
    int r = lane & 7, q = lane >> 3;

    float d[2][4];
#pragma unroll
    for (int nt = 0; nt < 2; nt++)
#pragma unroll
        for (int i = 0; i < 4; i++) d[nt][i] = 0.f;

#pragma unroll
    for (int k0 = 0; k0 < 64; k0 += 16) {
        unsigned a[4];
        ldsm_x4(a, smem_u32(h1s + (m0 + r + (q & 1) * 8) * LDP
                               + k0 + (q >> 1) * 8));
#pragma unroll
        for (int nt = 0; nt < 2; nt++) {
            unsigned bf[2];
            ldsm_x2t(bf, smem_u32(Ws + (k0 + r + (q & 1) * 8) * LDP
                                     + n0b + nt * 8));
            mma16816(d[nt], a, bf);
        }
    }

    int g = lane >> 2, tg = lane & 3;
    int nd0 = blockIdx.x * 64 + m0 + g, nd1 = nd0 + 8;
    float ds0 = (nd0 < n) ? g_dis[nd0] : 0.f;
    float ds1 = (nd1 < n) ? g_dis[nd1] : 0.f;
#pragma unroll
    for (int nt = 0; nt < 2; nt++) {
        int hcol = ((n0b + nt * 8) >> 1) + tg;
        if (nd0 < n)
            ht2[nd0 * 32 + hcol] = __floats2half2_rn(d[nt][0] * ds0, d[nt][1] * ds0);
        if (nd1 < n)
            ht2[nd1 * 32 + hcol] = __floats2half2_rn(d[nt][2] * ds1, d[nt][3] * ds1);
    }
}

// Aggregate layer 2 + warp-reduced pool atomics; LAST block computes FC.
__global__ void k_agg_pool_fc(const __half2* __restrict__ ht,
                              const float* __restrict__ b,
                              const void* __restrict__ batch,
                              const float* __restrict__ Wfc,
                              const float* __restrict__ bfc,
                              float* __restrict__ out, int n)
{
    int t = blockIdx.x * blockDim.x + threadIdx.x;
    int node = t >> 3;
    int l = t & 7;
    int lane = threadIdx.x & 31;

    float4 r0 = make_float4(0.f, 0.f, 0.f, 0.f);
    float4 r1 = make_float4(0.f, 0.f, 0.f, 0.f);
    int gph = -1;

    if (node < n) {
        float acc[8];
        gather_sum(ht, node, l, acc);

        float ds = g_dis[node];
        const float4* b4 = (const float4*)b;
        float4 b0 = b4[l * 2], b1 = b4[l * 2 + 1];
        r0.x = fmaxf(acc[0] * ds + b0.x, 0.f);
        r0.y = fmaxf(acc[1] * ds + b0.y, 0.f);
        r0.z = fmaxf(acc[2] * ds + b0.z, 0.f);
        r0.w = fmaxf(acc[3] * ds + b0.w, 0.f);
        r1.x = fmaxf(acc[4] * ds + b1.x, 0.f);
        r1.y = fmaxf(acc[5] * ds + b1.y, 0.f);
        r1.z = fmaxf(acc[6] * ds + b1.z, 0.f);
        r1.w = fmaxf(acc[7] * ds + b1.w, 0.f);

        gph = load_idx(batch, node, g_is32);
        if (l == 0) g_degi[node] = 0;    // restore zero-state for next replay
    }

    // ---- warp-level pool reduction (batch is sorted -> usually uniform) ----
    int g0 = __shfl_sync(~0u, gph, 0);
    bool uni = __all_sync(~0u, gph == g0);

    if (uni && g0 >= 0) {
#pragma unroll
        for (int o = 16; o >= 8; o >>= 1) {
            r0.x += __shfl_down_sync(~0u, r0.x, o);
            r0.y += __shfl_down_sync(~0u, r0.y, o);
            r0.z += __shfl_down_sync(~0u, r0.z, o);
            r0.w += __shfl_down_sync(~0u, r0.w, o);
            r1.x += __shfl_down_sync(~0u, r1.x, o);
            r1.y += __shfl_down_sync(~0u, r1.y, o);
            r1.z += __shfl_down_sync(~0u, r1.z, o);
            r1.w += __shfl_down_sync(~0u, r1.w, o);
        }
        if (lane < 8) {
            float* pp = (float*)g_pool + (size_t)g0 * DH + lane * 8;
            red_add_v4(pp, r0);
            red_add_v4(pp + 4, r1);
            if (lane == 0) atomicAdd(&g_cnt[g0], 4.0f);
        }
    } else if (gph >= 0) {
        float* pp = (float*)g_pool + (size_t)gph * DH + l * 8;
        red_add_v4(pp, r0);
        red_add_v4(pp + 4, r1);
        if (l == 0) atomicAdd(&g_cnt[gph], 1.0f);
    }

    // ---- last-block election, then FC ----
    __threadfence();
    __shared__ int isLast;
    if (threadIdx.x == 0) {
        int d = atomicAdd(&g_ctr_pool, 1);
        isLast = (d == (int)gridDim.x - 1);
        if (isLast) g_ctr_pool = 0;
    }
    __syncthreads();
    if (!isLast) return;

    for (int i = threadIdx.x; i < NG * NCLS; i += blockDim.x) {
        int g2 = i / NCLS, c = i % NCLS;
        float inv = 1.0f / fmaxf(g_cnt[g2], 1.0f);
        const float* pr = (const float*)g_pool + (size_t)g2 * DH;
        float acc = 0.f;
#pragma unroll
        for (int j = 0; j < DH; j++) acc += pr[j] * Wfc[j * NCLS + c];
        out[i] = acc * inv + bfc[c];
    }
    __syncthreads();
    for (int i = threadIdx.x; i < NG * 16; i += blockDim.x)
        g_pool[i] = make_float4(0.f, 0.f, 0.f, 0.f);
    if (threadIdx.x < NG) g_cnt[threadIdx.x] = 0.0f;
}

// ---------------- launcher ----------------
extern "C" void kernel_launch(void* const* d_in, const int* in_sizes, int n_in,
                              void* d_out, int out_size)
{
    const float* x   = (const float*)d_in[0];
    const void*  ei  = d_in[1];
    const void*  bat = d_in[2];
    const float* W1  = (const float*)d_in[3];
    const float* b1  = (const float*)d_in[4];
    const float* W2  = (const float*)d_in[5];
    const float* b2  = (const float*)d_in[6];
    const float* Wfc = (const float*)d_in[7];
    const float* bfc = (const float*)d_in[8];
    float* out = (float*)d_out;

    int n = in_sizes[0] / DH;       // nodes
    int E = in_sizes[1] / 2;        // edges

    static __half2* pA1 = nullptr; static __half2* pA2 = nullptr;
    if (!pA1) {
        void* tmp;
        cudaGetSymbolAddress(&tmp, g_Ah1); pA1 = (__half2*)tmp;
        cudaGetSymbolAddress(&tmp, g_Ah2); pA2 = (__half2*)tmp;
    }

    const int TB = 256;
    int nb_scan = (n + SCAN_B - 1) / SCAN_B;
    int q_e_blocks = ((E + 3) / 4 + TB - 1) / TB;
    int gemm_blocks = (n + 63) / 64;
    int fused_blocks = (n + 63) / 64;          // 64 nodes/block @ 512 threads
    int agg_blocks = ((long long)n * 8 + TB - 1) / TB;

    k_deg<<<q_e_blocks, TB>>>(ei, E);                                    // 1
    k_scan<<<nb_scan, SCAN_B>>>(n);                                      // 2
    k_gemm1_fill<<<gemm_blocks + q_e_blocks, TB>>>(x, W1, pA1, ei,
                                                   n, E, gemm_blocks);   // 3
    k_agg1_gemm2<<<fused_blocks, 512>>>(pA1, b1, W2, pA2, n);            // 4
    k_agg_pool_fc<<<agg_blocks, TB>>>(pA2, b2, bat, Wfc, bfc, out, n);   // 5
}

// round 16
// speedup vs baseline: 1.0662x; 1.0224x over previous
#include <cuda_runtime.h>
#include <cuda_fp16.h>
#include <cstdint>

// ---------------- problem constants (capacities) ----------------
#define NMAX   50000
#define EMAX   1600000
#define DH     64
#define NG     64
#define NCLS   10
#define SCAN_B 256

// ---------------- device scratch (no allocations allowed) -------
// Invariant at kernel_launch entry (BSS zero-init on first call, restored
// at tails of consumers every call): g_degi=0, g_pool=0, g_cnt=0,
// g_ctr_scan=0, g_ctr_pool=0.
__device__ __half2 g_Ah1[NMAX * 32];     // ht1 table, fp16 (row = 128B)
__device__ __half2 g_Ah2[NMAX * 32];     // ht2 table, fp16
__device__ float   g_dis[NMAX];          // rsqrt(deg+1)
__device__ int     g_degi[NMAX];         // edge in-degree (no self loop)
__device__ int     g_rowtmp[NMAX];       // per-block exclusive scan
__device__ int     g_bsum[(NMAX + SCAN_B - 1) / SCAN_B];
__device__ int     g_rank[EMAX];         // per-edge rank within its dst row
__device__ int     g_csr[EMAX];          // (src << 7) byte offsets, grouped by dst
__device__ float4  g_pool[NG * 16];      // per-graph feature sums
__device__ float   g_cnt[NG];            // per-graph node counts
__device__ int     g_is32;               // 1 if indices are int32 on the wire
__device__ int     g_ctr_scan;           // last-block counter for scan
__device__ int     g_ctr_pool;           // last-block counter for pool->fc

// ---------------- helpers ----------------
__device__ __forceinline__ int load_idx(const void* p, long long i, int is32) {
    if (is32) return ((const int*)p)[i];
    return (int)((const long long*)p)[i];
}

__device__ __forceinline__ void red_add_v4(float* addr, float4 v) {
    asm volatile("red.global.add.v4.f32 [%0], {%1,%2,%3,%4};"
                 :: "l"(addr), "f"(v.x), "f"(v.y), "f"(v.z), "f"(v.w)
                 : "memory");
}

__device__ __forceinline__ void red_add_f32(float* addr, float v) {
    asm volatile("red.global.add.f32 [%0], %1;"
                 :: "l"(addr), "f"(v) : "memory");
}

__device__ __forceinline__ void acc_u4(float* acc, uint4 u) {
    float2 f0 = __half22float2(((__half2*)&u)[0]);
    float2 f1 = __half22float2(((__half2*)&u)[1]);
    float2 f2 = __half22float2(((__half2*)&u)[2]);
    float2 f3 = __half22float2(((__half2*)&u)[3]);
    acc[0] += f0.x; acc[1] += f0.y; acc[2] += f1.x; acc[3] += f1.y;
    acc[4] += f2.x; acc[5] += f2.y; acc[6] += f3.x; acc[7] += f3.y;
}

__device__ __forceinline__ uint4 hadd4(uint4 a, uint4 b) {
    uint4 r;
    ((__half2*)&r)[0] = __hadd2(((__half2*)&a)[0], ((__half2*)&b)[0]);
    ((__half2*)&r)[1] = __hadd2(((__half2*)&a)[1], ((__half2*)&b)[1]);
    ((__half2*)&r)[2] = __hadd2(((__half2*)&a)[2], ((__half2*)&b)[2]);
    ((__half2*)&r)[3] = __hadd2(((__half2*)&a)[3], ((__half2*)&b)[3]);
    return r;
}

__device__ __forceinline__ int rowptr_of(int i) {
    return g_rowtmp[i] + g_bsum[i >> 8];
}

__device__ __forceinline__ uint4 pack8h(const float* v, float ds) {
    uint4 u;
    ((__half2*)&u)[0] = __floats2half2_rn(v[0] * ds, v[1] * ds);
    ((__half2*)&u)[1] = __floats2half2_rn(v[2] * ds, v[3] * ds);
    ((__half2*)&u)[2] = __floats2half2_rn(v[4] * ds, v[5] * ds);
    ((__half2*)&u)[3] = __floats2half2_rn(v[6] * ds, v[7] * ds);
    return u;
}

__device__ __forceinline__ uint4 gat(const char* base, int off, int l16) {
    return *(const uint4*)(base + off + l16);
}

// ---- tensor-core primitives ----
__device__ __forceinline__ uint32_t smem_u32(const void* p) {
    return (uint32_t)__cvta_generic_to_shared(p);
}

__device__ __forceinline__ void ldsm_x4(unsigned* r, uint32_t addr) {
    asm volatile("ldmatrix.sync.aligned.m8n8.x4.shared.b16 {%0,%1,%2,%3}, [%4];"
                 : "=r"(r[0]), "=r"(r[1]), "=r"(r[2]), "=r"(r[3]) : "r"(addr));
}

__device__ __forceinline__ void ldsm_x2t(unsigned* r, uint32_t addr) {
    asm volatile("ldmatrix.sync.aligned.m8n8.x2.trans.shared.b16 {%0,%1}, [%2];"
                 : "=r"(r[0]), "=r"(r[1]) : "r"(addr));
}

__device__ __forceinline__ void mma16816(float* d, const unsigned* a, const unsigned* b) {
    asm volatile("mma.sync.aligned.m16n8k16.row.col.f32.f16.f16.f32 "
                 "{%0,%1,%2,%3}, {%4,%5,%6,%7}, {%8,%9}, {%0,%1,%2,%3};"
                 : "+f"(d[0]), "+f"(d[1]), "+f"(d[2]), "+f"(d[3])
                 : "r"(a[0]), "r"(a[1]), "r"(a[2]), "r"(a[3]),
                   "r"(b[0]), "r"(b[1]));
}

#define LDP 72   // smem row pitch in halves (conflict-free ldmatrix)

// stage W[64][64] fp32 -> fp16 smem row-major, pitch LDP
__device__ __forceinline__ void stage_w(const float* __restrict__ W, __half* Ws) {
    for (int i2 = threadIdx.x; i2 < 64 * 32; i2 += blockDim.x) {
        int k = i2 >> 5, c = (i2 & 31) * 2;
        float2 w = ((const float2*)W)[i2];
        *(__half2*)(Ws + k * LDP + c) = __floats2half2_rn(w.x, w.y);
    }
}

// ---------------- kernels ----------------

// deg[dst] += 1 over edges, recording per-edge rank. 4 edges/thread.
__global__ void k_deg(const void* __restrict__ ei, int E) {
    __shared__ int flag;
    if (threadIdx.x == 0) flag = 0;
    __syncthreads();
    long long probe = ((const long long*)ei)[threadIdx.x];
    if ((unsigned long long)probe > 0xFFFFFFFFull) flag = 1;
    __syncthreads();
    int is32 = flag;

    int t = blockIdx.x * blockDim.x + threadIdx.x;
    if (t == 0) g_is32 = is32;
    int e = t * 4;
    if (e >= E) return;

    int d[4], cnt;
    if (is32) {
        const int* dstp = (const int*)ei + E;
        if (e + 3 < E) {
            int4 dv = ((const int4*)dstp)[t];
            d[0] = dv.x; d[1] = dv.y; d[2] = dv.z; d[3] = dv.w; cnt = 4;
        } else {
            cnt = E - e;
            for (int i = 0; i < cnt; i++) d[i] = dstp[e + i];
        }
    } else {
        const long long* dstp = (const long long*)ei + E;
        if (e + 3 < E) {
            longlong2 d0 = ((const longlong2*)dstp)[t * 2];
            longlong2 d1 = ((const longlong2*)dstp)[t * 2 + 1];
            d[0] = (int)d0.x; d[1] = (int)d0.y; d[2] = (int)d1.x; d[3] = (int)d1.y;
            cnt = 4;
        } else {
            cnt = E - e;
            for (int i = 0; i < cnt; i++) d[i] = (int)dstp[e + i];
        }
    }

    if (cnt == 4) {
        int4 r;
        r.x = atomicAdd(&g_degi[d[0]], 1);
        r.y = atomicAdd(&g_degi[d[1]], 1);
        r.z = atomicAdd(&g_degi[d[2]], 1);
        r.w = atomicAdd(&g_degi[d[3]], 1);
        ((int4*)g_rank)[t] = r;
    } else {
        for (int i = 0; i < cnt; i++)
            g_rank[e + i] = atomicAdd(&g_degi[d[i]], 1);
    }
}

// Fused scan: per-block exclusive scan + dis; last block scans block sums.
__global__ void k_scan(int n) {
    __shared__ int ws[8];
    __shared__ int isLast;
    int i = blockIdx.x * SCAN_B + threadIdx.x;
    int v = (i < n) ? g_degi[i] : 0;
    int lane = threadIdx.x & 31, w = threadIdx.x >> 5;
    int x = v;
#pragma unroll
    for (int o = 1; o < 32; o <<= 1) {
        int y = __shfl_up_sync(~0u, x, o);
        if (lane >= o) x += y;
    }
    if (lane == 31) ws[w] = x;
    __syncthreads();
    if (w == 0) {
        int y = (lane < 8) ? ws[lane] : 0;
#pragma unroll
        for (int o = 1; o < 8; o <<= 1) {
            int z = __shfl_up_sync(~0u, y, o);
            if (lane >= o) y += z;
        }
        if (lane < 8) ws[lane] = y;
    }
    __syncthreads();
    int incl = x + (w > 0 ? ws[w - 1] : 0);
    if (i < n) {
        g_rowtmp[i] = incl - v;
        g_dis[i] = rsqrtf((float)(v + 1));
    }
    if (threadIdx.x == SCAN_B - 1) g_bsum[blockIdx.x] = incl;

    __threadfence();
    if (threadIdx.x == 0) {
        int d = atomicAdd(&g_ctr_scan, 1);
        isLast = (d == (int)gridDim.x - 1);
        if (isLast) g_ctr_scan = 0;
    }
    __syncthreads();
    if (!isLast) return;

    int nb = gridDim.x;
    int v2 = (threadIdx.x < nb) ? g_bsum[threadIdx.x] : 0;
    int x2 = v2;
#pragma unroll
    for (int o = 1; o < 32; o <<= 1) {
        int y = __shfl_up_sync(~0u, x2, o);
        if (lane >= o) x2 += y;
    }
    __syncthreads();
    if (lane == 31) ws[w] = x2;
    __syncthreads();
    if (w == 0) {
        int y = (lane < 8) ? ws[lane] : 0;
#pragma unroll
        for (int o = 1; o < 8; o <<= 1) {
            int z = __shfl_up_sync(~0u, y, o);
            if (lane >= o) y += z;
        }
        if (lane < 8) ws[lane] = y;
    }
    __syncthreads();
    int excl = x2 - v2 + (w > 0 ? ws[w - 1] : 0);
    if (threadIdx.x < nb) g_bsum[threadIdx.x] = excl;
}

// Combined: blocks [0, gemmB) gemm1 via HMMA; rest: atomic-free CSR fill.
__global__ void k_gemm1_fill(const float* __restrict__ X,
                             const float* __restrict__ W,
                             __half2* __restrict__ ht,
                             const void* __restrict__ ei,
                             int n, int E, int gemmB)
{
    if (blockIdx.x < gemmB) {
        __shared__ __half sb[2 * 64 * LDP];   // 18KB: W1 + X tile
        __half* Ws = sb;
        __half* Xs = sb + 64 * LDP;

        stage_w(W, Ws);

        int r0b = blockIdx.x * 64;
        for (int i4 = threadIdx.x; i4 < 1024; i4 += blockDim.x) {
            int row = i4 >> 4, c4 = (i4 & 15) * 4;
            int grow = r0b + row;
            float4 xv = make_float4(0.f, 0.f, 0.f, 0.f);
            if (grow < n) xv = ((const float4*)(X + (size_t)grow * DH))[i4 & 15];
            *(__half2*)(Xs + row * LDP + c4)     = __floats2half2_rn(xv.x, xv.y);
            *(__half2*)(Xs + row * LDP + c4 + 2) = __floats2half2_rn(xv.z, xv.w);
        }
        __syncthreads();

        int w = threadIdx.x >> 5, lane = threadIdx.x & 31;
        int m0  = (w & 3) * 16;
        int n0b = (w >> 2) * 32;
        int r = lane & 7, q = lane >> 3;

        float d[4][4];
#pragma unroll
        for (int nt = 0; nt < 4; nt++)
#pragma unroll
            for (int i = 0; i < 4; i++) d[nt][i] = 0.f;

#pragma unroll
        for (int k0 = 0; k0 < 64; k0 += 16) {
            unsigned a[4];
            ldsm_x4(a, smem_u32(Xs + (m0 + r + (q & 1) * 8) * LDP
                                   + k0 + (q >> 1) * 8));
#pragma unroll
            for (int nt = 0; nt < 4; nt++) {
                unsigned bf[2];
                ldsm_x2t(bf, smem_u32(Ws + (k0 + r + (q & 1) * 8) * LDP
                                         + n0b + nt * 8));
                mma16816(d[nt], a, bf);
            }
        }

        int g = lane >> 2, tg = lane & 3;
        int row0 = r0b + m0 + g, row1 = row0 + 8;
        float ds0 = (row0 < n) ? g_dis[row0] : 0.f;
        float ds1 = (row1 < n) ? g_dis[row1] : 0.f;
#pragma unroll
        for (int nt = 0; nt < 4; nt++) {
            int hcol = ((n0b + nt * 8) >> 1) + tg;
            if (row0 < n)
                ht[row0 * 32 + hcol] = __floats2half2_rn(d[nt][0] * ds0, d[nt][1] * ds0);
            if (row1 < n)
                ht[row1 * 32 + hcol] = __floats2half2_rn(d[nt][2] * ds1, d[nt][3] * ds1);
        }
        return;
    }

    // ---- fill: atomic-free CSR scatter, 4 edges/thread ----
    int t = (blockIdx.x - gemmB) * blockDim.x + threadIdx.x;
    int e = t * 4;
    if (e >= E) return;
    int is32 = g_is32;
    int s[4], d[4], r[4], cnt;
    if (is32) {
        const int* srcp = (const int*)ei;
        const int* dstp = srcp + E;
        if (e + 3 < E) {
            int4 sv = ((const int4*)srcp)[t];
            int4 dv = ((const int4*)dstp)[t];
            int4 rv = ((const int4*)g_rank)[t];
            s[0] = sv.x; s[1] = sv.y; s[2] = sv.z; s[3] = sv.w;
            d[0] = dv.x; d[1] = dv.y; d[2] = dv.z; d[3] = dv.w;
            r[0] = rv.x; r[1] = rv.y; r[2] = rv.z; r[3] = rv.w;
            cnt = 4;
        } else {
            cnt = E - e;
            for (int i = 0; i < cnt; i++) {
                s[i] = srcp[e + i]; d[i] = dstp[e + i]; r[i] = g_rank[e + i];
            }
        }
    } else {
        const long long* srcp = (const long long*)ei;
        const long long* dstp = srcp + E;
        if (e + 3 < E) {
            longlong2 s0 = ((const longlong2*)srcp)[t * 2];
            longlong2 s1 = ((const longlong2*)srcp)[t * 2 + 1];
            longlong2 d0 = ((const longlong2*)dstp)[t * 2];
            longlong2 d1 = ((const longlong2*)dstp)[t * 2 + 1];
            int4 rv = ((const int4*)g_rank)[t];
            s[0] = (int)s0.x; s[1] = (int)s0.y; s[2] = (int)s1.x; s[3] = (int)s1.y;
            d[0] = (int)d0.x; d[1] = (int)d0.y; d[2] = (int)d1.x; d[3] = (int)d1.y;
            r[0] = rv.x; r[1] = rv.y; r[2] = rv.z; r[3] = rv.w;
            cnt = 4;
        } else {
            cnt = E - e;
            for (int i = 0; i < cnt; i++) {
                s[i] = (int)srcp[e + i]; d[i] = (int)dstp[e + i]; r[i] = g_rank[e + i];
            }
        }
    }
#pragma unroll
    for (int i = 0; i < 4; i++) {
        if (i < cnt) {
            int p = rowptr_of(d[i]) + r[i];
            g_csr[p] = s[i] << 7;
        }
    }
}

// shared gather-sum: fp32 acc[8] = sum of ht rows (self + neighbors)
__device__ __forceinline__ void gather_sum(const __half2* __restrict__ ht,
                                           int node, int l, float* acc)
{
    const char* hb = (const char*)ht;
    int l16 = l << 4;
#pragma unroll
    for (int j = 0; j < 8; j++) acc[j] = 0.f;
    acc_u4(acc, gat(hb, node << 7, l16));   // self loop

    int k = rowptr_of(node);
    int e = k + g_degi[node];
    for (; k + 8 <= e; k += 8) {
        int o0 = g_csr[k],     o1 = g_csr[k + 1];
        int o2 = g_csr[k + 2], o3 = g_csr[k + 3];
        int o4 = g_csr[k + 4], o5 = g_csr[k + 5];
        int o6 = g_csr[k + 6], o7 = g_csr[k + 7];
        uint4 v0 = gat(hb, o0, l16), v1 = gat(hb, o1, l16);
        uint4 v2 = gat(hb, o2, l16), v3 = gat(hb, o3, l16);
        uint4 v4 = gat(hb, o4, l16), v5 = gat(hb, o5, l16);
        uint4 v6 = gat(hb, o6, l16), v7 = gat(hb, o7, l16);
        uint4 t0 = hadd4(hadd4(v0, v1), hadd4(v2, v3));
        uint4 t1 = hadd4(hadd4(v4, v5), hadd4(v6, v7));
        acc_u4(acc, hadd4(t0, t1));
    }
    for (; k + 4 <= e; k += 4) {
        int o0 = g_csr[k],     o1 = g_csr[k + 1];
        int o2 = g_csr[k + 2], o3 = g_csr[k + 3];
        uint4 v0 = gat(hb, o0, l16), v1 = gat(hb, o1, l16);
        uint4 v2 = gat(hb, o2, l16), v3 = gat(hb, o3, l16);
        acc_u4(acc, hadd4(hadd4(v0, v1), hadd4(v2, v3)));
    }
    for (; k < e; k++) acc_u4(acc, gat(hb, g_csr[k], l16));
}

// Fused: agg over ht1 -> h1 (smem fp16) -> HMMA gemv W2 -> ht2 (fp16).
// 512 threads = 64 nodes/block; 16 warps cover the 64x64 gemv tile.
__global__ void k_agg1_gemm2(const __half2* __restrict__ ht1,
                             const float* __restrict__ b,
                             const float* __restrict__ W2,
                             __half2* __restrict__ ht2, int n)
{
    __shared__ __half sb[64 * LDP + 64 * LDP];   // W2 (9KB) + h1 tile (9KB)
    __half* Ws  = sb;
    __half* h1s = sb + 64 * LDP;

    stage_w(W2, Ws);

    int node_l = threadIdx.x >> 3;          // 0..63
    int node = blockIdx.x * 64 + node_l;
    int l = threadIdx.x & 7;

    float hv[8];
#pragma unroll
    for (int j = 0; j < 8; j++) hv[j] = 0.f;

    if (node < n) {
        float acc[8];
        gather_sum(ht1, node, l, acc);
        float ds = g_dis[node];
        const float4* b4 = (const float4*)b;
        float4 b0 = b4[l * 2], b1 = b4[l * 2 + 1];
        hv[0] = fmaxf(acc[0] * ds + b0.x, 0.f);
        hv[1] = fmaxf(acc[1] * ds + b0.y, 0.f);
        hv[2] = fmaxf(acc[2] * ds + b0.z, 0.f);
        hv[3] = fmaxf(acc[3] * ds + b0.w, 0.f);
        hv[4] = fmaxf(acc[4] * ds + b1.x, 0.f);
        hv[5] = fmaxf(acc[5] * ds + b1.y, 0.f);
        hv[6] = fmaxf(acc[6] * ds + b1.z, 0.f);
        hv[7] = fmaxf(acc[7] * ds + b1.w, 0.f);
    }
    *(uint4*)(h1s + node_l * LDP + l * 8) = pack8h(hv, 1.0f);
    __syncthreads();

    int w = threadIdx.x >> 5, lane = threadIdx.x & 31;
    int m0  = (w & 3) * 16;
    int n0b = (w >> 2) * 16;
    int r = lane & 7, q = lane >> 3;

    float d[2][4];
#pragma unroll
    for (int nt = 0; nt < 2; nt++)
#pragma unroll
        for (int i = 0; i < 4; i++) d[nt][i] = 0.f;

#pragma unroll
    for (int k0 = 0; k0 < 64; k0 += 16) {
        unsigned a[4];
        ldsm_x4(a, smem_u32(h1s + (m0 + r + (q & 1) * 8) * LDP
                               + k0 + (q >> 1) * 8));
#pragma unroll
        for (int nt = 0; nt < 2; nt++) {
            unsigned bf[2];
            ldsm_x2t(bf, smem_u32(Ws + (k0 + r + (q & 1) * 8) * LDP
                                     + n0b + nt * 8));
            mma16816(d[nt], a, bf);
        }
    }

    int g = lane >> 2, tg = lane & 3;
    int nd0 = blockIdx.x * 64 + m0 + g, nd1 = nd0 + 8;
    float ds0 = (nd0 < n) ? g_dis[nd0] : 0.f;
    float ds1 = (nd1 < n) ? g_dis[nd1] : 0.f;
#pragma unroll
    for (int nt = 0; nt < 2; nt++) {
        int hcol = ((n0b + nt * 8) >> 1) + tg;
        if (nd0 < n)
            ht2[nd0 * 32 + hcol] = __floats2half2_rn(d[nt][0] * ds0, d[nt][1] * ds0);
        if (nd1 < n)
            ht2[nd1 * 32 + hcol] = __floats2half2_rn(d[nt][2] * ds1, d[nt][3] * ds1);
    }
}

// Aggregate layer 2 + two-level (warp then block) reduced pool atomics;
// LAST block computes FC and restores state.
__global__ void k_agg_pool_fc(const __half2* __restrict__ ht,
                              const float* __restrict__ b,
                              const void* __restrict__ batch,
                              const float* __restrict__ Wfc,
                              const float* __restrict__ bfc,
                              float* __restrict__ out, int n)
{
    __shared__ float sp[8][64];   // per-warp partial pool rows
    __shared__ int   sg[8];       // per-warp graph id (-1 empty, -2 mixed)

    int t = blockIdx.x * blockDim.x + threadIdx.x;
    int node = t >> 3;
    int l = t & 7;
    int lane = threadIdx.x & 31;
    int w = threadIdx.x >> 5;

    float4 r0 = make_float4(0.f, 0.f, 0.f, 0.f);
    float4 r1 = make_float4(0.f, 0.f, 0.f, 0.f);
    int gph = -1;

    if (node < n) {
        float acc[8];
        gather_sum(ht, node, l, acc);

        float ds = g_dis[node];
        const float4* b4 = (const float4*)b;
        float4 b0 = b4[l * 2], b1 = b4[l * 2 + 1];
        r0.x = fmaxf(acc[0] * ds + b0.x, 0.f);
        r0.y = fmaxf(acc[1] * ds + b0.y, 0.f);
        r0.z = fmaxf(acc[2] * ds + b0.z, 0.f);
        r0.w = fmaxf(acc[3] * ds + b0.w, 0.f);
        r1.x = fmaxf(acc[4] * ds + b1.x, 0.f);
        r1.y = fmaxf(acc[5] * ds + b1.y, 0.f);
        r1.z = fmaxf(acc[6] * ds + b1.z, 0.f);
        r1.w = fmaxf(acc[7] * ds + b1.w, 0.f);

        gph = load_idx(batch, node, g_is32);
        if (l == 0) g_degi[node] = 0;    // restore zero-state for next replay
    }

    // ---- warp-level reduction ----
    int g0 = __shfl_sync(~0u, gph, 0);
    bool uni = __all_sync(~0u, gph == g0);

    if (uni && g0 >= 0) {
#pragma unroll
        for (int o = 16; o >= 8; o >>= 1) {
            r0.x += __shfl_down_sync(~0u, r0.x, o);
            r0.y += __shfl_down_sync(~0u, r0.y, o);
            r0.z += __shfl_down_sync(~0u, r0.z, o);
            r0.w += __shfl_down_sync(~0u, r0.w, o);
            r1.x += __shfl_down_sync(~0u, r1.x, o);
            r1.y += __shfl_down_sync(~0u, r1.y, o);
            r1.z += __shfl_down_sync(~0u, r1.z, o);
            r1.w += __shfl_down_sync(~0u, r1.w, o);
        }
        if (lane < 8) {
            *(float4*)&sp[w][lane * 8]     = r0;
            *(float4*)&sp[w][lane * 8 + 4] = r1;
        }
    }
    if (lane == 0) sg[w] = uni ? g0 : -2;
    __syncthreads();

    // ---- block-level check ----
    int gb = sg[0];
    bool blockUni = (gb >= 0);
    if (blockUni) {
#pragma unroll
        for (int w2 = 1; w2 < 8; w2++)
            if (sg[w2] != gb) { blockUni = false; break; }
    }

    if (blockUni) {
        // all 32 nodes valid & same graph: 64 scalar REDs + 1 cnt RED
        if (threadIdx.x < 64) {
            float s = 0.f;
#pragma unroll
            for (int w2 = 0; w2 < 8; w2++) s += sp[w2][threadIdx.x];
            red_add_f32((float*)g_pool + (size_t)gb * DH + threadIdx.x, s);
            if (threadIdx.x == 0) red_add_f32(&g_cnt[gb], 32.0f);
        }
    } else {
        if (uni && g0 >= 0) {
            if (lane < 8) {
                float* pp = (float*)g_pool + (size_t)g0 * DH + lane * 8;
                red_add_v4(pp, r0);
                red_add_v4(pp + 4, r1);
                if (lane == 0) red_add_f32(&g_cnt[g0], 4.0f);
            }
        } else if (gph >= 0) {
            float* pp = (float*)g_pool + (size_t)gph * DH + l * 8;
            red_add_v4(pp, r0);
            red_add_v4(pp + 4, r1);
            if (l == 0) red_add_f32(&g_cnt[gph], 1.0f);
        }
    }

    // ---- last-block election, then FC ----
    __threadfence();
    __shared__ int isLast;
    if (threadIdx.x == 0) {
        int d = atomicAdd(&g_ctr_pool, 1);
        isLast = (d == (int)gridDim.x - 1);
        if (isLast) g_ctr_pool = 0;
    }
    __syncthreads();
    if (!isLast) return;

    for (int i = threadIdx.x; i < NG * NCLS; i += blockDim.x) {
        int g2 = i / NCLS, c = i % NCLS;
        float inv = 1.0f / fmaxf(g_cnt[g2], 1.0f);
        const float* pr = (const float*)g_pool + (size_t)g2 * DH;
        float acc = 0.f;
#pragma unroll
        for (int j = 0; j < DH; j++) acc += pr[j] * Wfc[j * NCLS + c];
        out[i] = acc * inv + bfc[c];
    }
    __syncthreads();
    for (int i = threadIdx.x; i < NG * 16; i += blockDim.x)
        g_pool[i] = make_float4(0.f, 0.f, 0.f, 0.f);
    if (threadIdx.x < NG) g_cnt[threadIdx.x] = 0.0f;
}

// ---------------- launcher ----------------
extern "C" void kernel_launch(void* const* d_in, const int* in_sizes, int n_in,
                              void* d_out, int out_size)
{
    const float* x   = (const float*)d_in[0];
    const void*  ei  = d_in[1];
    const void*  bat = d_in[2];
    const float* W1  = (const float*)d_in[3];
    const float* b1  = (const float*)d_in[4];
    const float* W2  = (const float*)d_in[5];
    const float* b2  = (const float*)d_in[6];
    const float* Wfc = (const float*)d_in[7];
    const float* bfc = (const float*)d_in[8];
    float* out = (float*)d_out;

    int n = in_sizes[0] / DH;       // nodes
    int E = in_sizes[1] / 2;        // edges

    static __half2* pA1 = nullptr; static __half2* pA2 = nullptr;
    if (!pA1) {
        void* tmp;
        cudaGetSymbolAddress(&tmp, g_Ah1); pA1 = (__half2*)tmp;
        cudaGetSymbolAddress(&tmp, g_Ah2); pA2 = (__half2*)tmp;
    }

    const int TB = 256;
    int nb_scan = (n + SCAN_B - 1) / SCAN_B;
    int q_e_blocks = ((E + 3) / 4 + TB - 1) / TB;
    int gemm_blocks = (n + 63) / 64;
    int fused_blocks = (n + 63) / 64;          // 64 nodes/block @ 512 threads
    int agg_blocks = ((long long)n * 8 + TB - 1) / TB;

    k_deg<<<q_e_blocks, TB>>>(ei, E);                                    // 1
    k_scan<<<nb_scan, SCAN_B>>>(n);                                      // 2
    k_gemm1_fill<<<gemm_blocks + q_e_blocks, TB>>>(x, W1, pA1, ei,
                                                   n, E, gemm_blocks);   // 3
    k_agg1_gemm2<<<fused_blocks, 512>>>(pA1, b1, W2, pA2, n);            // 4
    k_agg_pool_fc<<<agg_blocks, TB>>>(pA2, b2, bat, Wfc, bfc, out, n);   // 5
}